// round 9
// baseline (speedup 1.0000x reference)
#include <cuda_runtime.h>
#include <cuda_fp16.h>
#include <cstdint>

#define S_  2048
#define D_  64
#define NBH 32
#define TQ  256
#define TK  128
#define NKT (S_/TK)
#define NTH 512
#define PH  72            // padded smem row stride in halves (144B)
#define RB  144           // row stride bytes

// ---- smem byte offsets ----
#define KB0 0
#define KB1 18432
#define VB0 36864
#define VB1 55296
#define ORED 73728        // 256 floats
#define OINV 74752        // 256 floats
#define SMEM_BYTES 75776  // 2 CTAs/SM: 151552 <= 228KB

// fp16 scratch (preconverted inputs; q pre-scaled by 1/sqrt(D))
#define NELEM (NBH * S_ * D_)
__device__ __half g_q16[NELEM];
__device__ __half g_k16[NELEM];
__device__ __half g_v16[NELEM];

__device__ __forceinline__ uint32_t smem_u32(const void* p) {
    uint32_t a;
    asm("{ .reg .u64 t; cvta.to.shared.u64 t, %1; cvt.u32.u64 %0, t; }"
        : "=r"(a) : "l"(p));
    return a;
}
__device__ __forceinline__ void ldsm4(uint32_t a, uint32_t r[4]) {
    asm volatile("ldmatrix.sync.aligned.m8n8.x4.shared.b16 {%0,%1,%2,%3}, [%4];"
        : "=r"(r[0]), "=r"(r[1]), "=r"(r[2]), "=r"(r[3]) : "r"(a));
}
__device__ __forceinline__ void ldsm4t(uint32_t a, uint32_t r[4]) {
    asm volatile("ldmatrix.sync.aligned.m8n8.x4.trans.shared.b16 {%0,%1,%2,%3}, [%4];"
        : "=r"(r[0]), "=r"(r[1]), "=r"(r[2]), "=r"(r[3]) : "r"(a));
}
__device__ __forceinline__ void mmah(float c[4], const uint32_t a[4],
                                     const uint32_t b0, const uint32_t b1) {
    asm volatile("mma.sync.aligned.m16n8k16.row.col.f32.f16.f16.f32 "
        "{%0,%1,%2,%3}, {%4,%5,%6,%7}, {%8,%9}, {%0,%1,%2,%3};"
        : "+f"(c[0]), "+f"(c[1]), "+f"(c[2]), "+f"(c[3])
        : "r"(a[0]), "r"(a[1]), "r"(a[2]), "r"(a[3]), "r"(b0), "r"(b1));
}
__device__ __forceinline__ uint32_t packh2(float x, float y) {
    __half2 h = __floats2half2_rn(x, y);
    return *(uint32_t*)&h;
}
#define CPA(d, s) asm volatile("cp.async.cg.shared.global [%0], [%1], 16;" \
                               :: "r"(d), "l"(s) : "memory")
#define CPC()     asm volatile("cp.async.commit_group;" ::: "memory")
#define CPW(n)    asm volatile("cp.async.wait_group %0;" :: "n"(n) : "memory")

// fetch a 128-row x 64-half tile (row-major, 128B/row) into padded smem
__device__ __forceinline__ void fetch_tile(uint32_t sdst, const __half* g, int tid) {
    #pragma unroll
    for (int i = 0; i < 2; i++) {
        int idx = i * NTH + tid;
        int row = idx >> 3, ch = idx & 7;
        CPA(sdst + (uint32_t)(row * RB + ch * 16),
            (const char*)g + (size_t)row * 128 + ch * 16);
    }
}

// ------------------- preconvert: fp32 -> fp16 -------------------
__global__ __launch_bounds__(256) void conv16(
    const float* __restrict__ q, const float* __restrict__ k,
    const float* __restrict__ v)
{
    int i = (blockIdx.x * 256 + threadIdx.x) * 4;
    const float* src; __half* dst; float sc;
    if (blockIdx.y == 0)      { src = q; dst = g_q16; sc = 0.125f; }
    else if (blockIdx.y == 1) { src = k; dst = g_k16; sc = 1.0f; }
    else                      { src = v; dst = g_v16; sc = 1.0f; }
    float4 x = *(const float4*)(src + i);
    uint2 o;
    o.x = packh2(x.x * sc, x.y * sc);
    o.y = packh2(x.z * sc, x.w * sc);
    *(uint2*)(dst + i) = o;
}

// ------------------- main attention kernel -------------------
__global__ __launch_bounds__(NTH, 2) void attn_hmma(
    float* __restrict__ out, float* __restrict__ attn)
{
    extern __shared__ char sm[];
    const uint32_t sb = smem_u32(sm);
    const int tid = threadIdx.x;
    const int lane = tid & 31;
    const int w = tid >> 5;          // 0..15
    const int half = w >> 3;         // 0: q-rows 0-127, 1: 128-255
    const int m0 = (w & 7) * 16;     // row strip within the half
    const int bh = blockIdx.y;
    const int qrow0 = blockIdx.x * TQ;
    const size_t base = (size_t)bh * S_ * D_;
    const int g8 = lane >> 3;

    // per-lane ldsm offsets (within a tile buffer)
    const uint32_t koff = (uint32_t)((((g8 >> 1) * 8 + (lane & 7)) * PH +
                                     (g8 & 1) * 8) * 2);
    const uint32_t voff = (uint32_t)((((lane & 7) + ((lane >> 3) & 1) * 8) * PH) * 2 +
                                     (lane >> 4) * 16);

    const __half* kg = g_k16 + base;
    const __half* vg = g_v16 + base;

    // ---- prologue: Q halves -> KB0/KB1, read fragments ----
    fetch_tile(sb + KB0, g_q16 + base + (size_t)qrow0 * D_, tid);           CPC();
    fetch_tile(sb + KB1, g_q16 + base + (size_t)(qrow0 + 128) * D_, tid);   CPC();
    CPW(0);
    __syncthreads();

    uint32_t aq[4][4];
    {
        int row = lane & 15;
        int colh = (lane >> 4) << 3;
        uint32_t qb = sb + (half ? KB1 : KB0);
        #pragma unroll
        for (int ks = 0; ks < 4; ks++)
            ldsm4(qb + (uint32_t)(((m0 + row) * PH + ks * 16 + colh) * 2),
                  aq[ks]);
    }
    __syncthreads();   // all warps done reading Q before K overwrites

    // ================= sweep 1: rowsums =================
    fetch_tile(sb + KB0, kg, tid);              CPC();
    fetch_tile(sb + KB1, kg + 128 * D_, tid);   CPC();

    float rs0 = 0.f, rs1 = 0.f;
    for (int kt = 0; kt < NKT; kt++) {
        CPW(1);
        __syncthreads();
        const uint32_t kb = sb + ((kt & 1) ? KB1 : KB0) + koff;
        #pragma unroll
        for (int c = 0; c < 8; c++) {
            float a0[4] = {0.f,0.f,0.f,0.f}, a1[4] = {0.f,0.f,0.f,0.f};
            #pragma unroll
            for (int ks = 0; ks < 4; ks++) {
                uint32_t b[4];
                ldsm4(kb + (uint32_t)((c * 16 * PH + ks * 16) * 2), b);
                mmah(a0, aq[ks], b[0], b[1]);
                mmah(a1, aq[ks], b[2], b[3]);
            }
            rs0 += __expf(a0[0]) + __expf(a0[1]) + __expf(a1[0]) + __expf(a1[1]);
            rs1 += __expf(a0[2]) + __expf(a0[3]) + __expf(a1[2]) + __expf(a1[3]);
        }
        __syncthreads();
        if (kt + 2 < NKT) {
            fetch_tile(sb + ((kt & 1) ? KB1 : KB0), kg + (size_t)(kt + 2) * 128 * D_, tid);
            CPC();
        }
    }
    rs0 += __shfl_xor_sync(0xFFFFFFFF, rs0, 1);
    rs0 += __shfl_xor_sync(0xFFFFFFFF, rs0, 2);
    rs1 += __shfl_xor_sync(0xFFFFFFFF, rs1, 1);
    rs1 += __shfl_xor_sync(0xFFFFFFFF, rs1, 2);
    __syncthreads();
    if ((lane & 3) == 0) {
        ((float*)(sm + ORED))[half * 128 + m0 + (lane >> 2)] = rs0;
        ((float*)(sm + ORED))[half * 128 + m0 + 8 + (lane >> 2)] = rs1;
    }
    __syncthreads();
    if (tid < 256)
        ((float*)(sm + OINV))[tid] = 1.0f / ((float*)(sm + ORED))[tid];
    __syncthreads();
    const float inv0 = ((float*)(sm + OINV))[half * 128 + m0 + (lane >> 2)];
    const float inv1 = ((float*)(sm + OINV))[half * 128 + m0 + 8 + (lane >> 2)];

    // ============ sweep 2: scores, normalized attn, fused AV ============
    float oacc[8][4];
    #pragma unroll
    for (int d = 0; d < 8; d++)
        #pragma unroll
        for (int i = 0; i < 4; i++) oacc[d][i] = 0.f;

    fetch_tile(sb + KB0, kg, tid);
    fetch_tile(sb + VB0, vg, tid);                 CPC();
    fetch_tile(sb + KB1, kg + 128 * D_, tid);
    fetch_tile(sb + VB1, vg + 128 * D_, tid);      CPC();

    for (int kt = 0; kt < NKT; kt++) {
        CPW(1);
        __syncthreads();
        const uint32_t kb = sb + ((kt & 1) ? KB1 : KB0) + koff;
        const uint32_t vb = sb + ((kt & 1) ? VB1 : VB0) + voff;

        float* arow0 = attn +
            ((size_t)(bh * S_ + qrow0 + half * 128 + m0 + (lane >> 2))) * S_
            + kt * TK + (lane & 3) * 2;
        float* arow1 = arow0 + (size_t)8 * S_;

        #pragma unroll
        for (int c = 0; c < 8; c++) {      // 16 kv cols per chunk
            float a0[4] = {0.f,0.f,0.f,0.f}, a1[4] = {0.f,0.f,0.f,0.f};
            #pragma unroll
            for (int ks = 0; ks < 4; ks++) {
                uint32_t b[4];
                ldsm4(kb + (uint32_t)((c * 16 * PH + ks * 16) * 2), b);
                mmah(a0, aq[ks], b[0], b[1]);
                mmah(a1, aq[ks], b[2], b[3]);
            }
            float p00 = __expf(a0[0]) * inv0;
            float p01 = __expf(a0[1]) * inv0;
            float p02 = __expf(a0[2]) * inv1;
            float p03 = __expf(a0[3]) * inv1;
            float p10 = __expf(a1[0]) * inv0;
            float p11 = __expf(a1[1]) * inv0;
            float p12 = __expf(a1[2]) * inv1;
            float p13 = __expf(a1[3]) * inv1;
            *(float2*)(arow0 + c * 16)     = make_float2(p00, p01);
            *(float2*)(arow1 + c * 16)     = make_float2(p02, p03);
            *(float2*)(arow0 + c * 16 + 8) = make_float2(p10, p11);
            *(float2*)(arow1 + c * 16 + 8) = make_float2(p12, p13);

            uint32_t ap[4];
            ap[0] = packh2(p00, p01);
            ap[1] = packh2(p02, p03);
            ap[2] = packh2(p10, p11);
            ap[3] = packh2(p12, p13);

            #pragma unroll
            for (int d2 = 0; d2 < 4; d2++) {
                uint32_t bv[4];
                ldsm4t(vb + (uint32_t)(c * 16 * PH * 2 + d2 * 32), bv);
                mmah(oacc[2*d2],     ap, bv[0], bv[1]);
                mmah(oacc[2*d2 + 1], ap, bv[2], bv[3]);
            }
        }
        __syncthreads();
        if (kt + 2 < NKT) {
            fetch_tile(sb + ((kt & 1) ? KB1 : KB0), kg + (size_t)(kt + 2) * 128 * D_, tid);
            fetch_tile(sb + ((kt & 1) ? VB1 : VB0), vg + (size_t)(kt + 2) * 128 * D_, tid);
            CPC();
        }
    }

    // ================= epilogue: write out (already normalized) =================
    float* orow0 = out +
        ((size_t)(bh * S_ + qrow0 + half * 128 + m0 + (lane >> 2))) * D_
        + (lane & 3) * 2;
    float* orow1 = orow0 + (size_t)8 * D_;
    #pragma unroll
    for (int dt = 0; dt < 8; dt++) {
        *(float2*)(orow0 + dt * 8) = make_float2(oacc[dt][0], oacc[dt][1]);
        *(float2*)(orow1 + dt * 8) = make_float2(oacc[dt][2], oacc[dt][3]);
    }
}

extern "C" void kernel_launch(void* const* d_in, const int* in_sizes, int n_in,
                              void* d_out, int out_size)
{
    const float* q = (const float*)d_in[0];
    const float* k = (const float*)d_in[1];
    const float* v = (const float*)d_in[2];
    float* out  = (float*)d_out;                    // [B,H,S,D]
    float* attn = out + (size_t)NBH * S_ * D_;      // [B,H,S,S]

    dim3 gc(NELEM / (256 * 4), 3);
    conv16<<<gc, 256>>>(q, k, v);

    cudaFuncSetAttribute(attn_hmma,
                         cudaFuncAttributeMaxDynamicSharedMemorySize, SMEM_BYTES);
    dim3 g(S_ / TQ, NBH);
    attn_hmma<<<g, NTH, SMEM_BYTES>>>(out, attn);
}

// round 10
// speedup vs baseline: 1.1025x; 1.1025x over previous
#include <cuda_runtime.h>
#include <cuda_fp16.h>
#include <cstdint>

#define S_  2048
#define D_  64
#define NBH 32
#define TQ  128
#define TK  128
#define NKT (S_/TK)
#define PH  72            // padded smem row stride in halves (144B)
#define RB  144           // row stride bytes
#define TILEB 18432       // 128 * 144

// ---- main-kernel smem ----
#define KB0 0
#define KB1 18432
#define VB0 36864
#define VB1 55296
#define SMEM_C 73728      // 3 CTAs/SM

// ---- rowsum-kernel smem ----
#define SMEM_B 36864      // 2 K buffers; 5 CTAs/SM

// fp16 scratch (q pre-scaled by 0.125*log2e so exp(s) == 2^(q16.k16))
#define NELEM (NBH * S_ * D_)
__device__ __half g_q16[NELEM];
__device__ __half g_k16[NELEM];
__device__ __half g_v16[NELEM];
__device__ float  g_inv[NBH * S_];

__device__ __forceinline__ uint32_t smem_u32(const void* p) {
    uint32_t a;
    asm("{ .reg .u64 t; cvta.to.shared.u64 t, %1; cvt.u32.u64 %0, t; }"
        : "=r"(a) : "l"(p));
    return a;
}
__device__ __forceinline__ void ldsm4(uint32_t a, uint32_t r[4]) {
    asm volatile("ldmatrix.sync.aligned.m8n8.x4.shared.b16 {%0,%1,%2,%3}, [%4];"
        : "=r"(r[0]), "=r"(r[1]), "=r"(r[2]), "=r"(r[3]) : "r"(a));
}
__device__ __forceinline__ void ldsm4t(uint32_t a, uint32_t r[4]) {
    asm volatile("ldmatrix.sync.aligned.m8n8.x4.trans.shared.b16 {%0,%1,%2,%3}, [%4];"
        : "=r"(r[0]), "=r"(r[1]), "=r"(r[2]), "=r"(r[3]) : "r"(a));
}
__device__ __forceinline__ void mmah(float c[4], const uint32_t a[4],
                                     const uint32_t b0, const uint32_t b1) {
    asm volatile("mma.sync.aligned.m16n8k16.row.col.f32.f16.f16.f32 "
        "{%0,%1,%2,%3}, {%4,%5,%6,%7}, {%8,%9}, {%0,%1,%2,%3};"
        : "+f"(c[0]), "+f"(c[1]), "+f"(c[2]), "+f"(c[3])
        : "r"(a[0]), "r"(a[1]), "r"(a[2]), "r"(a[3]), "r"(b0), "r"(b1));
}
__device__ __forceinline__ uint32_t packh2(float x, float y) {
    __half2 h = __floats2half2_rn(x, y);
    return *(uint32_t*)&h;
}
__device__ __forceinline__ float ex2f(float x) {   // 2^x, single MUFU
    float r;
    asm("ex2.approx.f32 %0, %1;" : "=f"(r) : "f"(x));
    return r;
}
// sum of 2^x over a packed fp16 pair (1 MUFU for 2 exps)
__device__ __forceinline__ float ex2_h2_sum(float x, float y) {
    uint32_t h = packh2(x, y), e;
    asm("ex2.approx.f16x2 %0, %1;" : "=r"(e) : "r"(h));
    float2 f = __half22float2(*(__half2*)&e);
    return f.x + f.y;
}
#define CPA(d, s) asm volatile("cp.async.cg.shared.global [%0], [%1], 16;" \
                               :: "r"(d), "l"(s) : "memory")
#define CPC()     asm volatile("cp.async.commit_group;" ::: "memory")
#define CPW(n)    asm volatile("cp.async.wait_group %0;" :: "n"(n) : "memory")

// fetch a 128-row x 64-half tile (row-major, 128B/row) into padded smem
__device__ __forceinline__ void fetch_tile(uint32_t sdst, const __half* g, int tid) {
    #pragma unroll
    for (int i = 0; i < 4; i++) {
        int idx = i * 256 + tid;
        int row = idx >> 3, ch = idx & 7;
        CPA(sdst + (uint32_t)(row * RB + ch * 16),
            (const char*)g + (size_t)row * 128 + ch * 16);
    }
}

// ------------------- preconvert: fp32 -> fp16 -------------------
__global__ __launch_bounds__(256) void conv16(
    const float* __restrict__ q, const float* __restrict__ k,
    const float* __restrict__ v)
{
    int i = (blockIdx.x * 256 + threadIdx.x) * 4;
    const float* src; __half* dst; float sc;
    if (blockIdx.y == 0)      { src = q; dst = g_q16; sc = 0.125f * 1.44269504f; }
    else if (blockIdx.y == 1) { src = k; dst = g_k16; sc = 1.0f; }
    else                      { src = v; dst = g_v16; sc = 1.0f; }
    float4 x = *(const float4*)(src + i);
    uint2 o;
    o.x = packh2(x.x * sc, x.y * sc);
    o.y = packh2(x.z * sc, x.w * sc);
    *(uint2*)(dst + i) = o;
}

// ------------------- kernel B: rowsums (high occupancy) -------------------
__global__ __launch_bounds__(256, 5) void rowsums(void)
{
    extern __shared__ char sm[];
    const uint32_t sb = smem_u32(sm);
    const int tid = threadIdx.x;
    const int lane = tid & 31;
    const int w = tid >> 5;
    const int m0 = w * 16;
    const int bh = blockIdx.y;
    const int qrow0 = blockIdx.x * TQ;
    const size_t base = (size_t)bh * S_ * D_;
    const int g8 = lane >> 3;
    const uint32_t koff = (uint32_t)((((g8 >> 1) * 8 + (lane & 7)) * PH +
                                     (g8 & 1) * 8) * 2);
    const __half* kg = g_k16 + base;

    // Q -> KB0, read fragments, then reuse KB0 for K
    fetch_tile(sb + KB0, g_q16 + base + (size_t)qrow0 * D_, tid); CPC();
    CPW(0);
    __syncthreads();
    uint32_t aq[4][4];
    {
        int row = lane & 15;
        int colh = (lane >> 4) << 3;
        #pragma unroll
        for (int ks = 0; ks < 4; ks++)
            ldsm4(sb + KB0 + (uint32_t)(((m0 + row) * PH + ks * 16 + colh) * 2),
                  aq[ks]);
    }
    __syncthreads();

    fetch_tile(sb + KB0, kg, tid);              CPC();
    fetch_tile(sb + KB1, kg + 128 * D_, tid);   CPC();

    float rs0 = 0.f, rs1 = 0.f;
    for (int kt = 0; kt < NKT; kt++) {
        CPW(1);
        __syncthreads();
        const uint32_t kb = sb + ((kt & 1) ? KB1 : KB0) + koff;
        #pragma unroll
        for (int c = 0; c < 8; c++) {
            float a0[4] = {0.f,0.f,0.f,0.f}, a1[4] = {0.f,0.f,0.f,0.f};
            #pragma unroll
            for (int ks = 0; ks < 4; ks++) {
                uint32_t b[4];
                ldsm4(kb + (uint32_t)((c * 16 * PH + ks * 16) * 2), b);
                mmah(a0, aq[ks], b[0], b[1]);
                mmah(a1, aq[ks], b[2], b[3]);
            }
            rs0 += ex2_h2_sum(a0[0], a0[1]) + ex2_h2_sum(a1[0], a1[1]);
            rs1 += ex2_h2_sum(a0[2], a0[3]) + ex2_h2_sum(a1[2], a1[3]);
        }
        __syncthreads();
        if (kt + 2 < NKT) {
            fetch_tile(sb + ((kt & 1) ? KB1 : KB0),
                       kg + (size_t)(kt + 2) * 128 * D_, tid);
            CPC();
        }
    }
    rs0 += __shfl_xor_sync(0xFFFFFFFF, rs0, 1);
    rs0 += __shfl_xor_sync(0xFFFFFFFF, rs0, 2);
    rs1 += __shfl_xor_sync(0xFFFFFFFF, rs1, 1);
    rs1 += __shfl_xor_sync(0xFFFFFFFF, rs1, 2);
    if ((lane & 3) == 0) {
        int r = bh * S_ + qrow0 + m0 + (lane >> 2);
        g_inv[r]     = 1.0f / rs0;
        g_inv[r + 8] = 1.0f / rs1;
    }
}

// ------------------- kernel C: attn + AV -------------------
__global__ __launch_bounds__(256, 3) void attn_hmma(
    float* __restrict__ out, float* __restrict__ attn)
{
    extern __shared__ char sm[];
    const uint32_t sb = smem_u32(sm);
    const int tid = threadIdx.x;
    const int lane = tid & 31;
    const int w = tid >> 5;
    const int m0 = w * 16;
    const int bh = blockIdx.y;
    const int qrow0 = blockIdx.x * TQ;
    const size_t base = (size_t)bh * S_ * D_;
    const int g8 = lane >> 3;

    const uint32_t koff = (uint32_t)((((g8 >> 1) * 8 + (lane & 7)) * PH +
                                     (g8 & 1) * 8) * 2);
    const uint32_t voff = (uint32_t)((((lane & 7) + ((lane >> 3) & 1) * 8) * PH) * 2 +
                                     (lane >> 4) * 16);

    const __half* kg = g_k16 + base;
    const __half* vg = g_v16 + base;

    // Q -> KB0, fragments, inv loads
    fetch_tile(sb + KB0, g_q16 + base + (size_t)qrow0 * D_, tid); CPC();
    const float inv0 = g_inv[bh * S_ + qrow0 + m0 + (lane >> 2)];
    const float inv1 = g_inv[bh * S_ + qrow0 + m0 + 8 + (lane >> 2)];
    CPW(0);
    __syncthreads();
    uint32_t aq[4][4];
    {
        int row = lane & 15;
        int colh = (lane >> 4) << 3;
        #pragma unroll
        for (int ks = 0; ks < 4; ks++)
            ldsm4(sb + KB0 + (uint32_t)(((m0 + row) * PH + ks * 16 + colh) * 2),
                  aq[ks]);
    }
    __syncthreads();

    float oacc[8][4];
    #pragma unroll
    for (int d = 0; d < 8; d++)
        #pragma unroll
        for (int i = 0; i < 4; i++) oacc[d][i] = 0.f;

    fetch_tile(sb + KB0, kg, tid);
    fetch_tile(sb + VB0, vg, tid);                 CPC();
    fetch_tile(sb + KB1, kg + 128 * D_, tid);
    fetch_tile(sb + VB1, vg + 128 * D_, tid);      CPC();

    for (int kt = 0; kt < NKT; kt++) {
        CPW(1);
        __syncthreads();
        const uint32_t kb = sb + ((kt & 1) ? KB1 : KB0) + koff;
        const uint32_t vb = sb + ((kt & 1) ? VB1 : VB0) + voff;

        float* arow0 = attn + ((size_t)(bh * S_ + qrow0 + m0 + (lane >> 2))) * S_
                       + kt * TK + (lane & 3) * 2;
        float* arow1 = arow0 + (size_t)8 * S_;

        #pragma unroll
        for (int c = 0; c < 8; c++) {      // 16 kv cols per chunk
            float a0[4] = {0.f,0.f,0.f,0.f}, a1[4] = {0.f,0.f,0.f,0.f};
            #pragma unroll
            for (int ks = 0; ks < 4; ks++) {
                uint32_t b[4];
                ldsm4(kb + (uint32_t)((c * 16 * PH + ks * 16) * 2), b);
                mmah(a0, aq[ks], b[0], b[1]);
                mmah(a1, aq[ks], b[2], b[3]);
            }
            // V fragments issued before the exp block (overlap MUFU with LSU)
            uint32_t bv0[4];
            ldsm4t(vb + (uint32_t)(c * 16 * PH * 2), bv0);

            float p00 = ex2f(a0[0]) * inv0;
            float p01 = ex2f(a0[1]) * inv0;
            float p02 = ex2f(a0[2]) * inv1;
            float p03 = ex2f(a0[3]) * inv1;
            float p10 = ex2f(a1[0]) * inv0;
            float p11 = ex2f(a1[1]) * inv0;
            float p12 = ex2f(a1[2]) * inv1;
            float p13 = ex2f(a1[3]) * inv1;

            uint32_t ap[4];
            ap[0] = packh2(p00, p01);
            ap[1] = packh2(p02, p03);
            ap[2] = packh2(p10, p11);
            ap[3] = packh2(p12, p13);

            mmah(oacc[0], ap, bv0[0], bv0[1]);
            mmah(oacc[1], ap, bv0[2], bv0[3]);
            #pragma unroll
            for (int d2 = 1; d2 < 4; d2++) {
                uint32_t bv[4];
                ldsm4t(vb + (uint32_t)(c * 16 * PH * 2 + d2 * 32), bv);
                mmah(oacc[2*d2],     ap, bv[0], bv[1]);
                mmah(oacc[2*d2 + 1], ap, bv[2], bv[3]);
            }

            *(float2*)(arow0 + c * 16)     = make_float2(p00, p01);
            *(float2*)(arow1 + c * 16)     = make_float2(p02, p03);
            *(float2*)(arow0 + c * 16 + 8) = make_float2(p10, p11);
            *(float2*)(arow1 + c * 16 + 8) = make_float2(p12, p13);
        }
        __syncthreads();
        if (kt + 2 < NKT) {
            fetch_tile(sb + ((kt & 1) ? KB1 : KB0), kg + (size_t)(kt + 2) * 128 * D_, tid);
            fetch_tile(sb + ((kt & 1) ? VB1 : VB0), vg + (size_t)(kt + 2) * 128 * D_, tid);
            CPC();
        }
    }

    // ---- epilogue: write out (already normalized) ----
    float* orow0 = out + ((size_t)(bh * S_ + qrow0 + m0 + (lane >> 2))) * D_
                   + (lane & 3) * 2;
    float* orow1 = orow0 + (size_t)8 * D_;
    #pragma unroll
    for (int dt = 0; dt < 8; dt++) {
        *(float2*)(orow0 + dt * 8) = make_float2(oacc[dt][0], oacc[dt][1]);
        *(float2*)(orow1 + dt * 8) = make_float2(oacc[dt][2], oacc[dt][3]);
    }
}

extern "C" void kernel_launch(void* const* d_in, const int* in_sizes, int n_in,
                              void* d_out, int out_size)
{
    const float* q = (const float*)d_in[0];
    const float* k = (const float*)d_in[1];
    const float* v = (const float*)d_in[2];
    float* out  = (float*)d_out;                    // [B,H,S,D]
    float* attn = out + (size_t)NBH * S_ * D_;      // [B,H,S,S]

    dim3 gc(NELEM / (256 * 4), 3);
    conv16<<<gc, 256>>>(q, k, v);

    dim3 g(S_ / TQ, NBH);
    cudaFuncSetAttribute(rowsums,
                         cudaFuncAttributeMaxDynamicSharedMemorySize, SMEM_B);
    rowsums<<<g, 256, SMEM_B>>>();

    cudaFuncSetAttribute(attn_hmma,
                         cudaFuncAttributeMaxDynamicSharedMemorySize, SMEM_C);
    attn_hmma<<<g, 256, SMEM_C>>>(out, attn);
}

// round 12
// speedup vs baseline: 1.1447x; 1.0383x over previous
#include <cuda_runtime.h>
#include <cuda_fp16.h>
#include <cstdint>

#define S_  2048
#define D_  64
#define NBH 32
#define TQ  128
#define TK  128
#define NKT (S_/TK)
#define NQT (S_/TQ)
#define PH  72            // padded smem row stride in halves (144B)
#define RB  144           // row stride bytes

// kernel B smem: 2 K buffers
#define KB0 0
#define KB1 18432
#define SMEM_B 36864
// kernel C smem: 2 V buffers
#define VB0 0
#define VB1 18432
#define SMEM_C 36864

#define NELEM (NBH * S_ * D_)
__device__ __half g_q16[NELEM];   // q pre-scaled by 0.125*log2e
__device__ __half g_k16[NELEM];
__device__ __half g_v16[NELEM];
__device__ float  g_inv[NBH * S_];
// unnormalized p = 2^(q.k), fp16, stored in HMMA A-fragment layout:
// index = (((bh*NQT + qt)*NKT + kt)*8 + chunk)*256 + tid   (uint4 each)
#define PCNT (NBH * NQT * NKT * 8 * 256)
__device__ uint4  g_p[PCNT];

__device__ __forceinline__ uint32_t smem_u32(const void* p) {
    uint32_t a;
    asm("{ .reg .u64 t; cvta.to.shared.u64 t, %1; cvt.u32.u64 %0, t; }"
        : "=r"(a) : "l"(p));
    return a;
}
__device__ __forceinline__ void ldsm4(uint32_t a, uint32_t r[4]) {
    asm volatile("ldmatrix.sync.aligned.m8n8.x4.shared.b16 {%0,%1,%2,%3}, [%4];"
        : "=r"(r[0]), "=r"(r[1]), "=r"(r[2]), "=r"(r[3]) : "r"(a));
}
__device__ __forceinline__ void ldsm4t(uint32_t a, uint32_t r[4]) {
    asm volatile("ldmatrix.sync.aligned.m8n8.x4.trans.shared.b16 {%0,%1,%2,%3}, [%4];"
        : "=r"(r[0]), "=r"(r[1]), "=r"(r[2]), "=r"(r[3]) : "r"(a));
}
__device__ __forceinline__ void mmah(float c[4], const uint32_t a[4],
                                     const uint32_t b0, const uint32_t b1) {
    asm volatile("mma.sync.aligned.m16n8k16.row.col.f32.f16.f16.f32 "
        "{%0,%1,%2,%3}, {%4,%5,%6,%7}, {%8,%9}, {%0,%1,%2,%3};"
        : "+f"(c[0]), "+f"(c[1]), "+f"(c[2]), "+f"(c[3])
        : "r"(a[0]), "r"(a[1]), "r"(a[2]), "r"(a[3]), "r"(b0), "r"(b1));
}
__device__ __forceinline__ uint32_t packh2(float x, float y) {
    __half2 h = __floats2half2_rn(x, y);
    return *(uint32_t*)&h;
}
__device__ __forceinline__ float ex2f(float x) {
    float r;
    asm("ex2.approx.f32 %0, %1;" : "=f"(r) : "f"(x));
    return r;
}
#define CPA(d, s) asm volatile("cp.async.cg.shared.global [%0], [%1], 16;" \
                               :: "r"(d), "l"(s) : "memory")
#define CPC()     asm volatile("cp.async.commit_group;" ::: "memory")
#define CPW(n)    asm volatile("cp.async.wait_group %0;" :: "n"(n) : "memory")

__device__ __forceinline__ void fetch_tile(uint32_t sdst, const __half* g, int tid) {
    #pragma unroll
    for (int i = 0; i < 4; i++) {
        int idx = i * 256 + tid;
        int row = idx >> 3, ch = idx & 7;
        CPA(sdst + (uint32_t)(row * RB + ch * 16),
            (const char*)g + (size_t)row * 128 + ch * 16);
    }
}

// ------------------- preconvert: fp32 -> fp16 -------------------
__global__ __launch_bounds__(256) void conv16(
    const float* __restrict__ q, const float* __restrict__ k,
    const float* __restrict__ v)
{
    int i = (blockIdx.x * 256 + threadIdx.x) * 4;
    const float* src; __half* dst; float sc;
    if (blockIdx.y == 0)      { src = q; dst = g_q16; sc = 0.125f * 1.44269504f; }
    else if (blockIdx.y == 1) { src = k; dst = g_k16; sc = 1.0f; }
    else                      { src = v; dst = g_v16; sc = 1.0f; }
    float4 x = *(const float4*)(src + i);
    uint2 o;
    o.x = packh2(x.x * sc, x.y * sc);
    o.y = packh2(x.z * sc, x.w * sc);
    *(uint2*)(dst + i) = o;
}

// ------------- kernel B: QK^T, exp, rowsums, store unnormalized p -------------
__global__ __launch_bounds__(256, 5) void rowsums_p(void)
{
    extern __shared__ char sm[];
    const uint32_t sb = smem_u32(sm);
    const int tid = threadIdx.x;
    const int lane = tid & 31;
    const int w = tid >> 5;
    const int m0 = w * 16;
    const int bh = blockIdx.y;
    const int qt = blockIdx.x;
    const int qrow0 = qt * TQ;
    const size_t base = (size_t)bh * S_ * D_;
    const int g8 = lane >> 3;
    const uint32_t koff = (uint32_t)((((g8 >> 1) * 8 + (lane & 7)) * PH +
                                     (g8 & 1) * 8) * 2);
    const __half* kg = g_k16 + base;
    uint4* pout = g_p + (size_t)((bh * NQT + qt) * NKT) * 8 * 256 + tid;

    // Q -> KB0, read fragments, then reuse KB0 for K
    fetch_tile(sb + KB0, g_q16 + base + (size_t)qrow0 * D_, tid); CPC();
    CPW(0);
    __syncthreads();
    uint32_t aq[4][4];
    {
        int row = lane & 15;
        int colh = (lane >> 4) << 3;
        #pragma unroll
        for (int ks = 0; ks < 4; ks++)
            ldsm4(sb + KB0 + (uint32_t)(((m0 + row) * PH + ks * 16 + colh) * 2),
                  aq[ks]);
    }
    __syncthreads();

    fetch_tile(sb + KB0, kg, tid);              CPC();
    fetch_tile(sb + KB1, kg + 128 * D_, tid);   CPC();

    float rs0 = 0.f, rs1 = 0.f;
    for (int kt = 0; kt < NKT; kt++) {
        CPW(1);
        __syncthreads();
        const uint32_t kb = sb + ((kt & 1) ? KB1 : KB0) + koff;
        uint4* pt = pout + (size_t)kt * 8 * 256;
        #pragma unroll
        for (int c = 0; c < 8; c++) {
            float a0[4] = {0.f,0.f,0.f,0.f}, a1[4] = {0.f,0.f,0.f,0.f};
            #pragma unroll
            for (int ks = 0; ks < 4; ks++) {
                uint32_t b[4];
                ldsm4(kb + (uint32_t)((c * 16 * PH + ks * 16) * 2), b);
                mmah(a0, aq[ks], b[0], b[1]);
                mmah(a1, aq[ks], b[2], b[3]);
            }
            float e00 = ex2f(a0[0]), e01 = ex2f(a0[1]);
            float e02 = ex2f(a0[2]), e03 = ex2f(a0[3]);
            float e10 = ex2f(a1[0]), e11 = ex2f(a1[1]);
            float e12 = ex2f(a1[2]), e13 = ex2f(a1[3]);
            rs0 += e00 + e01 + e10 + e11;
            rs1 += e02 + e03 + e12 + e13;
            uint4 pk;
            pk.x = packh2(e00, e01);
            pk.y = packh2(e02, e03);
            pk.z = packh2(e10, e11);
            pk.w = packh2(e12, e13);
            pt[c * 256] = pk;
        }
        __syncthreads();
        if (kt + 2 < NKT) {
            fetch_tile(sb + ((kt & 1) ? KB1 : KB0),
                       kg + (size_t)(kt + 2) * 128 * D_, tid);
            CPC();
        }
    }
    rs0 += __shfl_xor_sync(0xFFFFFFFF, rs0, 1);
    rs0 += __shfl_xor_sync(0xFFFFFFFF, rs0, 2);
    rs1 += __shfl_xor_sync(0xFFFFFFFF, rs1, 1);
    rs1 += __shfl_xor_sync(0xFFFFFFFF, rs1, 2);
    if ((lane & 3) == 0) {
        int r = bh * S_ + qrow0 + m0 + (lane >> 2);
        g_inv[r]     = 1.0f / rs0;
        g_inv[r + 8] = 1.0f / rs1;
    }
}

// ---- kernel C: read p, write normalized attn, AV with RAW fp16 p,
//      normalize the AV result in the epilogue (single fp16 rounding of p) ----
__global__ __launch_bounds__(256, 4) void av_attn(
    float* __restrict__ out, float* __restrict__ attn)
{
    extern __shared__ char sm[];
    const uint32_t sb = smem_u32(sm);
    const int tid = threadIdx.x;
    const int lane = tid & 31;
    const int w = tid >> 5;
    const int m0 = w * 16;
    const int bh = blockIdx.y;
    const int qt = blockIdx.x;
    const int qrow0 = qt * TQ;
    const size_t base = (size_t)bh * S_ * D_;
    const uint32_t voff = (uint32_t)((((lane & 7) + ((lane >> 3) & 1) * 8) * PH) * 2 +
                                     (lane >> 4) * 16);
    const __half* vg = g_v16 + base;
    const uint4* pin = g_p + (size_t)((bh * NQT + qt) * NKT) * 8 * 256 + tid;

    const float inv0 = g_inv[bh * S_ + qrow0 + m0 + (lane >> 2)];
    const float inv1 = g_inv[bh * S_ + qrow0 + m0 + 8 + (lane >> 2)];

    fetch_tile(sb + VB0, vg, tid);              CPC();
    fetch_tile(sb + VB1, vg + 128 * D_, tid);   CPC();

    float oacc[8][4];
    #pragma unroll
    for (int d = 0; d < 8; d++)
        #pragma unroll
        for (int i = 0; i < 4; i++) oacc[d][i] = 0.f;

    for (int kt = 0; kt < NKT; kt++) {
        CPW(1);
        __syncthreads();
        const uint32_t vb = sb + ((kt & 1) ? VB1 : VB0) + voff;
        const uint4* pt = pin + (size_t)kt * 8 * 256;

        float* arow0 = attn + ((size_t)(bh * S_ + qrow0 + m0 + (lane >> 2))) * S_
                       + kt * TK + (lane & 3) * 2;
        float* arow1 = arow0 + (size_t)8 * S_;

        uint4 pk = pt[0];                    // prefetch chunk 0
        #pragma unroll
        for (int c = 0; c < 8; c++) {
            uint4 pk_n;
            if (c < 7) pk_n = pt[(c + 1) * 256];

            // AV with the RAW stored fp16 p (no re-rounding)
            uint32_t ap[4] = {pk.x, pk.y, pk.z, pk.w};
            #pragma unroll
            for (int d2 = 0; d2 < 4; d2++) {
                uint32_t bv[4];
                ldsm4t(vb + (uint32_t)(c * 16 * PH * 2 + d2 * 32), bv);
                mmah(oacc[2*d2],     ap, bv[0], bv[1]);
                mmah(oacc[2*d2 + 1], ap, bv[2], bv[3]);
            }

            // normalized attn output (fp32 multiply of the fp16 p)
            float2 f0 = __half22float2(*(__half2*)&pk.x);
            float2 f1 = __half22float2(*(__half2*)&pk.y);
            float2 f2 = __half22float2(*(__half2*)&pk.z);
            float2 f3 = __half22float2(*(__half2*)&pk.w);
            *(float2*)(arow0 + c * 16)     = make_float2(f0.x * inv0, f0.y * inv0);
            *(float2*)(arow1 + c * 16)     = make_float2(f1.x * inv1, f1.y * inv1);
            *(float2*)(arow0 + c * 16 + 8) = make_float2(f2.x * inv0, f2.y * inv0);
            *(float2*)(arow1 + c * 16 + 8) = make_float2(f3.x * inv1, f3.y * inv1);
            pk = pk_n;
        }
        __syncthreads();
        if (kt + 2 < NKT) {
            fetch_tile(sb + ((kt & 1) ? VB1 : VB0),
                       vg + (size_t)(kt + 2) * 128 * D_, tid);
            CPC();
        }
    }

    // ---- epilogue: out = oacc * inv (normalize once, here) ----
    float* orow0 = out + ((size_t)(bh * S_ + qrow0 + m0 + (lane >> 2))) * D_
                   + (lane & 3) * 2;
    float* orow1 = orow0 + (size_t)8 * D_;
    #pragma unroll
    for (int dt = 0; dt < 8; dt++) {
        *(float2*)(orow0 + dt * 8) = make_float2(oacc[dt][0] * inv0,
                                                 oacc[dt][1] * inv0);
        *(float2*)(orow1 + dt * 8) = make_float2(oacc[dt][2] * inv1,
                                                 oacc[dt][3] * inv1);
    }
}

extern "C" void kernel_launch(void* const* d_in, const int* in_sizes, int n_in,
                              void* d_out, int out_size)
{
    const float* q = (const float*)d_in[0];
    const float* k = (const float*)d_in[1];
    const float* v = (const float*)d_in[2];
    float* out  = (float*)d_out;                    // [B,H,S,D]
    float* attn = out + (size_t)NBH * S_ * D_;      // [B,H,S,S]

    dim3 gc(NELEM / (256 * 4), 3);
    conv16<<<gc, 256>>>(q, k, v);

    dim3 g(NQT, NBH);
    rowsums_p<<<g, 256, SMEM_B>>>();
    av_attn<<<g, 256, SMEM_C>>>(out, attn);
}

// round 15
// speedup vs baseline: 1.2114x; 1.0582x over previous
#include <cuda_runtime.h>
#include <cuda_fp16.h>
#include <cstdint>

#define S_  2048
#define D_  64
#define NBH 32
#define TQ  128
#define TK  128
#define NKT (S_/TK)
#define NQT (S_/TQ)
#define PH  72            // padded smem row stride in halves (144B)
#define RB  144           // row stride bytes

// smem: two tile buffers (K in phase B, V in phase C)
#define BUF0 0
#define BUF1 18432
#define SMEM_BYTES 36864  // 4 CTAs/SM

#define NELEM (NBH * S_ * D_)
__device__ __half g_q16[NELEM];   // q pre-scaled by 0.125*log2e
__device__ __half g_k16[NELEM];
__device__ __half g_v16[NELEM];
// unnormalized p = 2^(q.k), fp16, HMMA A-fragment layout:
// index = (((bh*NQT + qt)*NKT + kt)*8 + chunk)*256 + tid   (uint4 each)
#define PCNT (NBH * NQT * NKT * 8 * 256)
__device__ uint4  g_p[PCNT];

__device__ __forceinline__ uint32_t smem_u32(const void* p) {
    uint32_t a;
    asm("{ .reg .u64 t; cvta.to.shared.u64 t, %1; cvt.u32.u64 %0, t; }"
        : "=r"(a) : "l"(p));
    return a;
}
__device__ __forceinline__ void ldsm4(uint32_t a, uint32_t r[4]) {
    asm volatile("ldmatrix.sync.aligned.m8n8.x4.shared.b16 {%0,%1,%2,%3}, [%4];"
        : "=r"(r[0]), "=r"(r[1]), "=r"(r[2]), "=r"(r[3]) : "r"(a));
}
__device__ __forceinline__ void ldsm4t(uint32_t a, uint32_t r[4]) {
    asm volatile("ldmatrix.sync.aligned.m8n8.x4.trans.shared.b16 {%0,%1,%2,%3}, [%4];"
        : "=r"(r[0]), "=r"(r[1]), "=r"(r[2]), "=r"(r[3]) : "r"(a));
}
__device__ __forceinline__ void mmah(float c[4], const uint32_t a[4],
                                     const uint32_t b0, const uint32_t b1) {
    asm volatile("mma.sync.aligned.m16n8k16.row.col.f32.f16.f16.f32 "
        "{%0,%1,%2,%3}, {%4,%5,%6,%7}, {%8,%9}, {%0,%1,%2,%3};"
        : "+f"(c[0]), "+f"(c[1]), "+f"(c[2]), "+f"(c[3])
        : "r"(a[0]), "r"(a[1]), "r"(a[2]), "r"(a[3]), "r"(b0), "r"(b1));
}
__device__ __forceinline__ uint32_t packh2(float x, float y) {
    __half2 h = __floats2half2_rn(x, y);
    return *(uint32_t*)&h;
}
__device__ __forceinline__ float ex2f(float x) {
    float r;
    asm("ex2.approx.f32 %0, %1;" : "=f"(r) : "f"(x));
    return r;
}
// streaming (evict-first) global accesses for write-once / read-once data
__device__ __forceinline__ void stg_cs_u4(uint4* p, uint4 v) {
    asm volatile("st.global.cs.v4.u32 [%0], {%1,%2,%3,%4};"
        :: "l"(p), "r"(v.x), "r"(v.y), "r"(v.z), "r"(v.w) : "memory");
}
__device__ __forceinline__ uint4 ldg_cs_u4(const uint4* p) {
    uint4 v;
    asm volatile("ld.global.cs.v4.u32 {%0,%1,%2,%3}, [%4];"
        : "=r"(v.x), "=r"(v.y), "=r"(v.z), "=r"(v.w) : "l"(p));
    return v;
}
__device__ __forceinline__ void stg_cs_f2(float* p, float a, float b) {
    asm volatile("st.global.cs.v2.f32 [%0], {%1,%2};"
        :: "l"(p), "f"(a), "f"(b) : "memory");
}
#define CPA(d, s) asm volatile("cp.async.cg.shared.global [%0], [%1], 16;" \
                               :: "r"(d), "l"(s) : "memory")
#define CPC()     asm volatile("cp.async.commit_group;" ::: "memory")
#define CPW(n)    asm volatile("cp.async.wait_group %0;" :: "n"(n) : "memory")
// wait so that the CURRENT tile is complete: on the last iteration the
// current tile's group is the ONLY pending one, so we must drain to 0.
#define CPW_ITER(kt) do { if ((kt) + 1 < NKT) { CPW(1); } else { CPW(0); } } while (0)

__device__ __forceinline__ void fetch_tile(uint32_t sdst, const __half* g, int tid) {
    #pragma unroll
    for (int i = 0; i < 4; i++) {
        int idx = i * 256 + tid;
        int row = idx >> 3, ch = idx & 7;
        CPA(sdst + (uint32_t)(row * RB + ch * 16),
            (const char*)g + (size_t)row * 128 + ch * 16);
    }
}

// ------------------- preconvert: fp32 -> fp16 -------------------
__global__ __launch_bounds__(256) void conv16(
    const float* __restrict__ q, const float* __restrict__ k,
    const float* __restrict__ v)
{
    int i = (blockIdx.x * 256 + threadIdx.x) * 4;
    const float* src; __half* dst; float sc;
    if (blockIdx.y == 0)      { src = q; dst = g_q16; sc = 0.125f * 1.44269504f; }
    else if (blockIdx.y == 1) { src = k; dst = g_k16; sc = 1.0f; }
    else                      { src = v; dst = g_v16; sc = 1.0f; }
    float4 x = *(const float4*)(src + i);
    uint2 o;
    o.x = packh2(x.x * sc, x.y * sc);
    o.y = packh2(x.z * sc, x.w * sc);
    *(uint2*)(dst + i) = o;
}

// ---------------- fused attention: phase B then phase C per CTA ----------------
__global__ __launch_bounds__(256, 4) void attn_fused(
    float* __restrict__ out, float* __restrict__ attn)
{
    extern __shared__ char sm[];
    const uint32_t sb = smem_u32(sm);
    const int tid = threadIdx.x;
    const int lane = tid & 31;
    const int w = tid >> 5;
    const int m0 = w * 16;
    const int bh = blockIdx.y;
    const int qt = blockIdx.x;
    const int qrow0 = qt * TQ;
    const size_t base = (size_t)bh * S_ * D_;
    const int g8 = lane >> 3;
    const uint32_t koff = (uint32_t)((((g8 >> 1) * 8 + (lane & 7)) * PH +
                                     (g8 & 1) * 8) * 2);
    const uint32_t voff = (uint32_t)((((lane & 7) + ((lane >> 3) & 1) * 8) * PH) * 2 +
                                     (lane >> 4) * 16);
    const __half* kg = g_k16 + base;
    const __half* vg = g_v16 + base;
    uint4* pbase = g_p + (size_t)((bh * NQT + qt) * NKT) * 8 * 256 + tid;

    // ================= phase B: QK^T, exp, rowsums, store p =================
    float inv0, inv1;
    {
        // Q -> BUF0, fragments
        fetch_tile(sb + BUF0, g_q16 + base + (size_t)qrow0 * D_, tid); CPC();
        CPW(0);
        __syncthreads();
        uint32_t aq[4][4];
        {
            int row = lane & 15;
            int colh = (lane >> 4) << 3;
            #pragma unroll
            for (int ks = 0; ks < 4; ks++)
                ldsm4(sb + BUF0 + (uint32_t)(((m0 + row) * PH + ks * 16 + colh) * 2),
                      aq[ks]);
        }
        __syncthreads();

        fetch_tile(sb + BUF0, kg, tid);              CPC();
        fetch_tile(sb + BUF1, kg + 128 * D_, tid);   CPC();

        float rs0 = 0.f, rs1 = 0.f;
        for (int kt = 0; kt < NKT; kt++) {
            CPW_ITER(kt);                 // last iter: drain to 0 (fixes race)
            __syncthreads();
            const uint32_t kb = sb + ((kt & 1) ? BUF1 : BUF0) + koff;
            uint4* pt = pbase + (size_t)kt * 8 * 256;
            #pragma unroll
            for (int c = 0; c < 8; c++) {
                float a0[4] = {0.f,0.f,0.f,0.f}, a1[4] = {0.f,0.f,0.f,0.f};
                #pragma unroll
                for (int ks = 0; ks < 4; ks++) {
                    uint32_t b[4];
                    ldsm4(kb + (uint32_t)((c * 16 * PH + ks * 16) * 2), b);
                    mmah(a0, aq[ks], b[0], b[1]);
                    mmah(a1, aq[ks], b[2], b[3]);
                }
                float e00 = ex2f(a0[0]), e01 = ex2f(a0[1]);
                float e02 = ex2f(a0[2]), e03 = ex2f(a0[3]);
                float e10 = ex2f(a1[0]), e11 = ex2f(a1[1]);
                float e12 = ex2f(a1[2]), e13 = ex2f(a1[3]);
                rs0 += e00 + e01 + e10 + e11;
                rs1 += e02 + e03 + e12 + e13;
                uint4 pk;
                pk.x = packh2(e00, e01);
                pk.y = packh2(e02, e03);
                pk.z = packh2(e10, e11);
                pk.w = packh2(e12, e13);
                stg_cs_u4(&pt[c * 256], pk);
            }
            __syncthreads();
            if (kt + 2 < NKT) {
                fetch_tile(sb + ((kt & 1) ? BUF1 : BUF0),
                           kg + (size_t)(kt + 2) * 128 * D_, tid);
                CPC();
            }
        }
        rs0 += __shfl_xor_sync(0xFFFFFFFF, rs0, 1);
        rs0 += __shfl_xor_sync(0xFFFFFFFF, rs0, 2);
        rs1 += __shfl_xor_sync(0xFFFFFFFF, rs1, 1);
        rs1 += __shfl_xor_sync(0xFFFFFFFF, rs1, 2);
        inv0 = 1.0f / rs0;    // valid in all 4 lanes of the quad
        inv1 = 1.0f / rs1;
    }

    // ================= phase C: AV with raw p, normalized attn =================
    // (pending cp.async groups here: 0 — phase B drained with CPW(0))
    fetch_tile(sb + BUF0, vg, tid);              CPC();
    fetch_tile(sb + BUF1, vg + 128 * D_, tid);   CPC();

    float oacc[8][4];
    #pragma unroll
    for (int d = 0; d < 8; d++)
        #pragma unroll
        for (int i = 0; i < 4; i++) oacc[d][i] = 0.f;

    for (int kt = 0; kt < NKT; kt++) {
        CPW_ITER(kt);                     // last iter: drain to 0 (fixes race)
        __syncthreads();
        const uint32_t vb = sb + ((kt & 1) ? BUF1 : BUF0) + voff;
        const uint4* pt = pbase + (size_t)kt * 8 * 256;

        float* arow0 = attn + ((size_t)(bh * S_ + qrow0 + m0 + (lane >> 2))) * S_
                       + kt * TK + (lane & 3) * 2;
        float* arow1 = arow0 + (size_t)8 * S_;

        uint4 pk = ldg_cs_u4(&pt[0]);
        #pragma unroll
        for (int c = 0; c < 8; c++) {
            uint4 pk_n;
            if (c < 7) pk_n = ldg_cs_u4(&pt[(c + 1) * 256]);

            // AV with the RAW stored fp16 p (single rounding)
            uint32_t ap[4] = {pk.x, pk.y, pk.z, pk.w};
            #pragma unroll
            for (int d2 = 0; d2 < 4; d2++) {
                uint32_t bv[4];
                ldsm4t(vb + (uint32_t)(c * 16 * PH * 2 + d2 * 32), bv);
                mmah(oacc[2*d2],     ap, bv[0], bv[1]);
                mmah(oacc[2*d2 + 1], ap, bv[2], bv[3]);
            }

            // normalized attn output (fp32 multiply of the fp16 p)
            float2 f0 = __half22float2(*(__half2*)&pk.x);
            float2 f1 = __half22float2(*(__half2*)&pk.y);
            float2 f2 = __half22float2(*(__half2*)&pk.z);
            float2 f3 = __half22float2(*(__half2*)&pk.w);
            stg_cs_f2(arow0 + c * 16,     f0.x * inv0, f0.y * inv0);
            stg_cs_f2(arow1 + c * 16,     f1.x * inv1, f1.y * inv1);
            stg_cs_f2(arow0 + c * 16 + 8, f2.x * inv0, f2.y * inv0);
            stg_cs_f2(arow1 + c * 16 + 8, f3.x * inv1, f3.y * inv1);
            pk = pk_n;
        }
        __syncthreads();
        if (kt + 2 < NKT) {
            fetch_tile(sb + ((kt & 1) ? BUF1 : BUF0),
                       vg + (size_t)(kt + 2) * 128 * D_, tid);
            CPC();
        }
    }

    // ---- epilogue: out = oacc * inv ----
    float* orow0 = out + ((size_t)(bh * S_ + qrow0 + m0 + (lane >> 2))) * D_
                   + (lane & 3) * 2;
    float* orow1 = orow0 + (size_t)8 * D_;
    #pragma unroll
    for (int dt = 0; dt < 8; dt++) {
        *(float2*)(orow0 + dt * 8) = make_float2(oacc[dt][0] * inv0,
                                                 oacc[dt][1] * inv0);
        *(float2*)(orow1 + dt * 8) = make_float2(oacc[dt][2] * inv1,
                                                 oacc[dt][3] * inv1);
    }
}

extern "C" void kernel_launch(void* const* d_in, const int* in_sizes, int n_in,
                              void* d_out, int out_size)
{
    const float* q = (const float*)d_in[0];
    const float* k = (const float*)d_in[1];
    const float* v = (const float*)d_in[2];
    float* out  = (float*)d_out;                    // [B,H,S,D]
    float* attn = out + (size_t)NBH * S_ * D_;      // [B,H,S,S]

    dim3 gc(NELEM / (256 * 4), 3);
    conv16<<<gc, 256>>>(q, k, v);

    dim3 g(NQT, NBH);
    cudaFuncSetAttribute(attn_fused,
                         cudaFuncAttributeMaxDynamicSharedMemorySize, SMEM_BYTES);
    attn_fused<<<g, 256, SMEM_BYTES>>>(out, attn);
}